// round 7
// baseline (speedup 1.0000x reference)
#include <cuda_runtime.h>
#include <cuda_bf16.h>
#include <mma.h>
#include <cstdint>

using namespace nvcuda;

#define Bsz 8
#define Nn 1024
#define Ee 256
#define Dm 64
#define Hh 4
#define DH 16

// ======================= device scratch =======================
__device__ float d_qk[2][Bsz][Hh][DH][Nn];                 // q, k transposed [c][n]
__device__ float d_e [4][Bsz][Hh][Ee][DH];                 // eq, ek, ceq, cek
// MMA-ready padded bf16 rows (64 cols = 128B each):
//   d_ga row: [qhi(16) | qhi(16) | qlo(16) | 0(16)]   (gq pre-scaled by 1/8)
//   d_gb row: [khi(16) | klo(16) | khi(16) | 0(16)]
// => dot over k=0..47 = qhi*khi + qhi*klo + qlo*khi  (3-term bf16 split, err ~1e-5)
__device__ __nv_bfloat16 d_ga[2][Bsz][Hh][Nn][64];
__device__ __nv_bfloat16 d_gb[2][Bsz][Hh][Nn][64];

// ---------------- K1: emb -> q,k (transposed) ----------------
__global__ void k_qk(const float* __restrict__ x,
                     const float* __restrict__ W_emb, const float* __restrict__ b_emb,
                     const float* __restrict__ W_q,   const float* __restrict__ b_q,
                     const float* __restrict__ W_k,   const float* __restrict__ b_k) {
    int bn  = blockIdx.x;
    int tid = threadIdx.x;         // 0..63
    __shared__ float emb[64];
    float x0 = x[bn * 2 + 0];
    float x1 = x[bn * 2 + 1];
    emb[tid] = x0 * W_emb[tid] + x1 * W_emb[64 + tid] + b_emb[tid];
    __syncthreads();
    float q = b_q[tid], k = b_k[tid];
#pragma unroll
    for (int j = 0; j < 64; ++j) {
        float e = emb[j];
        q = fmaf(e, W_q[j * 64 + tid], q);
        k = fmaf(e, W_k[j * 64 + tid], k);
    }
    int b = bn >> 10, n = bn & 1023;
    int h = tid >> 4, c = tid & 15;
    d_qk[0][b][h][c][n] = q;
    d_qk[1][b][h][c][n] = k;
}

// ---------------- K2: edge projections ----------------
__global__ void k_edge(const float* __restrict__ edge, const float* __restrict__ cedge,
                       const float* __restrict__ W_eq,  const float* __restrict__ b_eq,
                       const float* __restrict__ W_ek,  const float* __restrict__ b_ek,
                       const float* __restrict__ W_ceq, const float* __restrict__ b_ceq,
                       const float* __restrict__ W_cek, const float* __restrict__ b_cek) {
    int i = blockIdx.x * blockDim.x + threadIdx.x;
    int c = i & 15;
    int r = (i >> 4) & 8191;
    int t = i >> 17;
    const float* src = (t < 2 ? edge : cedge) + r * 16;
    const float* W; const float* bb;
    if      (t == 0) { W = W_eq;  bb = b_eq;  }
    else if (t == 1) { W = W_ek;  bb = b_ek;  }
    else if (t == 2) { W = W_ceq; bb = b_ceq; }
    else             { W = W_cek; bb = b_cek; }
    float a = bb[c];
#pragma unroll
    for (int j = 0; j < 16; ++j) a = fmaf(src[j], W[j * 16 + c], a);
    (&d_e[0][0][0][0][0])[i] = a;
}

// ---------------- K3: gq/gk + div + bf16 hi/lo MMA-format emit ----------------
// grid: 2br * 8b * 16nt = 256 blocks; 1024 threads = 16 c x 64 n
__global__ void __launch_bounds__(1024, 1)
k_gextra(const float* __restrict__ G, const float* __restrict__ CG) {
    int bid = blockIdx.x;
    int nt = bid & 15;  bid >>= 4;
    int b  = bid & 7;   bid >>= 3;
    int br = bid;
    int tid = threadIdx.x;
    int c    = tid >> 6;        // 0..15
    int nloc = tid & 63;        // 0..63
    int nbase = nt * 64;

    const float* Gm  = (br ? CG : G) + (size_t)b * Ee * Nn;
    const float* eqb = &d_e[br * 2 + 0][b][0][0][0];   // [h][e][c]
    const float* ekb = &d_e[br * 2 + 1][b][0][0][0];

    __shared__ float sg[16][64];
    __shared__ float seq[4][16][16];
    __shared__ float sek[4][16][16];
    __shared__ float sq [4][64][16];    // results [h][nloc][c]
    __shared__ float sk2[4][64][16];

    float aq[4] = {0.f, 0.f, 0.f, 0.f};
    float ak[4] = {0.f, 0.f, 0.f, 0.f};
    float gsum = 0.f;

    for (int e0 = 0; e0 < Ee; e0 += 16) {
        __syncthreads();
        {
            int se = tid >> 6, sn = tid & 63;
            sg[se][sn] = Gm[(size_t)(e0 + se) * Nn + nbase + sn];
            int sh = tid >> 8, see = (tid >> 4) & 15, sc = tid & 15;
            seq[sh][see][sc] = eqb[(sh * Ee + e0 + see) * DH + sc];
            sek[sh][see][sc] = ekb[(sh * Ee + e0 + see) * DH + sc];
        }
        __syncthreads();
#pragma unroll
        for (int ee = 0; ee < 16; ++ee) {
            float g = sg[ee][nloc];
            gsum += g;
#pragma unroll
            for (int h = 0; h < 4; ++h) {
                aq[h] = fmaf(g, seq[h][ee][c], aq[h]);
                ak[h] = fmaf(g, sek[h][ee][c], ak[h]);
            }
        }
    }
    float rd = 1.0f / gsum;
    int n = nbase + nloc;
#pragma unroll
    for (int h = 0; h < 4; ++h) {
        float q = d_qk[0][b][h][c][n];
        float k = d_qk[1][b][h][c][n];
        sq [h][nloc][c] = (q + aq[h] * rd) * 0.125f;   // fold 1/sqrt(64)
        sk2[h][nloc][c] = (k + ak[h] * rd);
    }
    __syncthreads();

    // emit: 1024 threads -> 512 jobs x 2 halves. job = (h, nloc, qk); half = 32 bf16 (64B).
    {
        int half = tid & 1;
        int job  = tid >> 1;
        int qk   = job & 1;
        int nl   = (job >> 1) & 63;
        int h    = job >> 7;
        const float* src = qk ? &sk2[h][nl][0] : &sq[h][nl][0];
        __nv_bfloat16 hi[16]; __nv_bfloat16 lo[16];
#pragma unroll
        for (int j = 0; j < 16; ++j) {
            float v = src[j];
            hi[j] = __float2bfloat16(v);
            lo[j] = __float2bfloat16(v - __bfloat162float(hi[j]));
        }
        uint32_t u[16];
        if (half == 0) {
            // cols 0-31:  A: hi|hi   B: hi|lo
#pragma unroll
            for (int j = 0; j < 8; ++j)
                u[j] = (uint32_t)__bfloat16_as_ushort(hi[2 * j]) |
                       ((uint32_t)__bfloat16_as_ushort(hi[2 * j + 1]) << 16);
#pragma unroll
            for (int j = 0; j < 8; ++j) {
                __nv_bfloat16 a  = qk ? lo[2 * j]     : hi[2 * j];
                __nv_bfloat16 bq = qk ? lo[2 * j + 1] : hi[2 * j + 1];
                u[8 + j] = (uint32_t)__bfloat16_as_ushort(a) |
                           ((uint32_t)__bfloat16_as_ushort(bq) << 16);
            }
        } else {
            // cols 32-63: A: lo|0   B: hi|0
#pragma unroll
            for (int j = 0; j < 8; ++j) {
                __nv_bfloat16 a  = qk ? hi[2 * j]     : lo[2 * j];
                __nv_bfloat16 bq = qk ? hi[2 * j + 1] : lo[2 * j + 1];
                u[j] = (uint32_t)__bfloat16_as_ushort(a) |
                       ((uint32_t)__bfloat16_as_ushort(bq) << 16);
            }
#pragma unroll
            for (int j = 0; j < 8; ++j) u[8 + j] = 0u;
        }
        __nv_bfloat16* dstb = qk ? &d_gb[br][b][h][nbase + nl][0] : &d_ga[br][b][h][nbase + nl][0];
        uint4* dst = (uint4*)(dstb + half * 32);
        dst[0] = make_uint4(u[0], u[1], u[2], u[3]);
        dst[1] = make_uint4(u[4], u[5], u[6], u[7]);
        dst[2] = make_uint4(u[8], u[9], u[10], u[11]);
        dst[3] = make_uint4(u[12], u[13], u[14], u[15]);
    }
}

// ---------------- K4: scores via wmma (HMMA) + softmax ----------------
// grid: 2br*8b*4h*64rowchunk(16 rows) = 4096 blocks; 256 threads (8 warps).
// Warp w handles cols w*128..+127 (8 n-tiles of 16). K=48 (3 k-steps).
#define ESM_LD 1040
__global__ void __launch_bounds__(256, 2)
k_attn(float* __restrict__ out) {
    int bid = blockIdx.x;
    int rc = bid & 63;  bid >>= 6;
    int h  = bid & 3;   bid >>= 2;
    int b  = bid & 7;   bid >>= 3;
    int br = bid;
    int rbase = rc * 16;

    extern __shared__ float Esm[];   // [16][ESM_LD] = 65 KB
    __shared__ float s_inv[16];

    const __nv_bfloat16* ga = &d_ga[br][b][h][rbase][0];   // 16 x 64 (row-major, ldm 64)
    const __nv_bfloat16* gb = &d_gb[br][b][h][0][0];       // (k,n) at gb[n*64+k] = col-major ldm 64

    int tid = threadIdx.x;
    int warp = tid >> 5;

    wmma::fragment<wmma::matrix_a, 16, 16, 16, __nv_bfloat16, wmma::row_major> af[3];
    wmma::load_matrix_sync(af[0], ga + 0,  64);
    wmma::load_matrix_sync(af[1], ga + 16, 64);
    wmma::load_matrix_sync(af[2], ga + 32, 64);

#pragma unroll
    for (int j = 0; j < 8; ++j) {
        int n0 = warp * 128 + j * 16;
        wmma::fragment<wmma::matrix_b, 16, 16, 16, __nv_bfloat16, wmma::col_major> bf0, bf1, bf2;
        wmma::fragment<wmma::accumulator, 16, 16, 16, float> cf;
        wmma::fill_fragment(cf, 0.0f);
        wmma::load_matrix_sync(bf0, gb + (size_t)n0 * 64 + 0,  64);
        wmma::load_matrix_sync(bf1, gb + (size_t)n0 * 64 + 16, 64);
        wmma::load_matrix_sync(bf2, gb + (size_t)n0 * 64 + 32, 64);
        wmma::mma_sync(cf, af[0], bf0, cf);
        wmma::mma_sync(cf, af[1], bf1, cf);
        wmma::mma_sync(cf, af[2], bf2, cf);
#pragma unroll
        for (int e = 0; e < cf.num_elements; ++e)
            cf.x[e] = __expf(cf.x[e]);        // no max: softmax shift-invariant, scores bounded
        wmma::store_matrix_sync(&Esm[n0], cf, ESM_LD, wmma::mem_row_major);
    }
    __syncthreads();

    // rowsum: 16 rows x 16 partials; each thread sums 64 contiguous floats
    {
        int r = tid >> 4, tp = tid & 15;
        const float* row = &Esm[r * ESM_LD + tp * 64];
        float s = 0.f;
#pragma unroll
        for (int i = 0; i < 16; ++i) {
            float4 v = *(const float4*)(row + i * 4);
            s += v.x + v.y + v.z + v.w;
        }
#pragma unroll
        for (int o = 8; o; o >>= 1) s += __shfl_xor_sync(0xffffffffu, s, o);
        if (tp == 0) s_inv[r] = 1.0f / s;
    }
    __syncthreads();

    // normalize + coalesced float4 stores
    size_t obase = ((((size_t)br * Bsz + b) * Hh + h) * Nn + rbase) * (size_t)Nn;
    for (int i = tid; i < 4096; i += 256) {
        int r  = i >> 8;
        int c4 = (i & 255) << 2;
        float inv = s_inv[r];
        float4 v = *(const float4*)&Esm[r * ESM_LD + c4];
        v.x *= inv; v.y *= inv; v.z *= inv; v.w *= inv;
        *(float4*)(out + obase + (size_t)r * Nn + c4) = v;
    }
}

// ---------------- launcher ----------------
extern "C" void kernel_launch(void* const* d_in, const int* in_sizes, int n_in,
                              void* d_out, int out_size) {
    const float* x      = (const float*)d_in[0];
    const float* edge   = (const float*)d_in[1];
    const float* cedge  = (const float*)d_in[2];
    const float* G      = (const float*)d_in[3];
    const float* CG     = (const float*)d_in[4];
    const float* W_emb  = (const float*)d_in[5];
    const float* b_emb  = (const float*)d_in[6];
    const float* W_q    = (const float*)d_in[7];
    const float* b_q    = (const float*)d_in[8];
    const float* W_k    = (const float*)d_in[9];
    const float* b_k    = (const float*)d_in[10];
    const float* W_eq   = (const float*)d_in[11];
    const float* b_eq   = (const float*)d_in[12];
    const float* W_ek   = (const float*)d_in[13];
    const float* b_ek   = (const float*)d_in[14];
    const float* W_ceq  = (const float*)d_in[15];
    const float* b_ceq  = (const float*)d_in[16];
    const float* W_cek  = (const float*)d_in[17];
    const float* b_cek  = (const float*)d_in[18];
    float* out = (float*)d_out;

    cudaFuncSetAttribute(k_attn, cudaFuncAttributeMaxDynamicSharedMemorySize, 16 * ESM_LD * 4);

    k_qk<<<Bsz * Nn, 64>>>(x, W_emb, b_emb, W_q, b_q, W_k, b_k);
    k_edge<<<2048, 256>>>(edge, cedge, W_eq, b_eq, W_ek, b_ek, W_ceq, b_ceq, W_cek, b_cek);
    k_gextra<<<256, 1024>>>(G, CG);
    k_attn<<<4096, 256, 16 * ESM_LD * 4>>>(out);
}